// round 14
// baseline (speedup 1.0000x reference)
#include <cuda_runtime.h>
#include <cuda_bf16.h>
#include <cstdint>

// ---------------------------------------------------------------------------
// MACE invariant message passing:
//   h   = node_feats @ W_up
//   m   = h[sender] * edge_attrs * edge_feats[l_of_lm]   (per edge)
//   msg = segment_sum over receiver  (stored as bf16 hi/lo)
//   out = msg @ ( W_lin[l] @ W_skip[elem,l] / 16 )       (grouped by element)
// Output GEMM: warp-level mma.sync bf16 (HMMA) with hi/lo compensation,
// static tile ranges + software-pipelined A prefetch.
// ---------------------------------------------------------------------------

typedef unsigned long long u64;

#define N_MAX 6144
#define E_MAX 131072
#define NE_MAX 16
#define NG_MAX (NE_MAX * 4)
#define AST 68    // As row stride (floats) in the scalar GEMM (BM=64 + pad)

// Static device scratch (allocation-free per harness rules)
__device__ float d_h[(size_t)N_MAX * 128];
__device__ __nv_bfloat16 d_msg_hi[(size_t)N_MAX * 16 * 128];
__device__ __nv_bfloat16 d_msg_lo[(size_t)N_MAX * 16 * 128];
__device__ __nv_bfloat16 d_WcT_hi[(size_t)NG_MAX * 128 * 128];
__device__ __nv_bfloat16 d_WcT_lo[(size_t)NG_MAX * 128 * 128];
__device__ int   d_sorted[E_MAX];
__device__ int   d_counts[N_MAX];          // zero-init; scan re-zeroes after use
__device__ int   d_offsets[N_MAX + 1];
__device__ int   d_cursor[N_MAX];
__device__ int   d_node_by_elem[N_MAX];
__device__ int   d_elem_off[NE_MAX + 1];
__device__ int   d_elem_cur[NE_MAX];
__device__ int   d_tile_off[NG_MAX + 1];
__device__ int   d_tile_ctr;

// --------------------------- helpers ---------------------------------------
__device__ __forceinline__ uint32_t smem_u32(const void* p) {
    uint32_t a;
    asm("{ .reg .u64 t; cvta.to.shared.u64 t, %1; cvt.u32.u64 %0, t; }"
        : "=r"(a) : "l"(p));
    return a;
}

#define CP16(dst, src) \
    asm volatile("cp.async.cg.shared.global [%0], [%1], 16;" \
        :: "r"(dst), "l"(src) : "memory")
#define CP_COMMIT() asm volatile("cp.async.commit_group;" ::: "memory")
template <int W>
__device__ __forceinline__ void cp_wait() {
    asm volatile("cp.async.wait_group %0;" :: "n"(W) : "memory");
}

#define LDSM4(r0, r1, r2, r3, addr) \
    asm volatile("ldmatrix.sync.aligned.m8n8.x4.shared.b16 {%0,%1,%2,%3}, [%4];" \
        : "=r"(r0), "=r"(r1), "=r"(r2), "=r"(r3) : "r"(addr))

#define MMA16816(c, a, b) \
    asm volatile("mma.sync.aligned.m16n8k16.row.col.f32.bf16.bf16.f32 " \
        "{%0,%1,%2,%3}, {%4,%5,%6,%7}, {%8,%9}, {%0,%1,%2,%3};" \
        : "+f"((c)[0]), "+f"((c)[1]), "+f"((c)[2]), "+f"((c)[3]) \
        : "r"((a)[0]), "r"((a)[1]), "r"((a)[2]), "r"((a)[3]), \
          "r"((b)[0]), "r"((b)[1]))

// ---------------------------------------------------------------------------
// Fused GEMM kernel (scalar fp32, BM=64, BN=128, BK=16, acc 4x8 -> no spills):
//   z == 0          : h = node_feats @ W_up          (tiles over blockIdx.x)
//   z >= 1, x <= 1  : WcT[g] rows x*64..+63 = transpose(W_lin[l] @ W_skip[g]/16)
//   z >= 1, x >= 2  : helper blocks run the receiver histogram
// ---------------------------------------------------------------------------
__global__ __launch_bounds__(256) void gemm_fused_kernel(
    const float* __restrict__ node_feats,
    const float* __restrict__ W_up,
    const float* __restrict__ W_lin,
    const float* __restrict__ W_skip,
    const int*   __restrict__ recv,
    int N, int E, int NE)
{
    const float* A;
    const float* B;
    int M;
    float scale;
    int z = blockIdx.z;
    int g = z - 1;
    int row0;

    if (z == 0) {
        A = node_feats; B = W_up; M = N; scale = 1.0f;
        row0 = blockIdx.x * 64;
    } else {
        if (blockIdx.x >= 2) {
            int nb  = gridDim.x - 2;
            int id  = (z - 1) * nb + (blockIdx.x - 2);
            int tot = (int)(gridDim.z - 1) * nb;
            for (int i = id * 256 + threadIdx.x; i < E; i += tot * 256)
                atomicAdd(&d_counts[recv[i]], 1);
            return;
        }
        int l = g & 3;
        A = W_lin  + (size_t)l * 16384;
        B = W_skip + (size_t)g * 16384;
        M = 128; scale = 1.0f / 16.0f;
        row0 = blockIdx.x * 64;
    }

    __shared__ float As[16 * AST];
    __shared__ float Bs[16 * 128];

    int tid = threadIdx.x;
    int ty = tid >> 4;      // 0..15 -> 4-row group
    int tx = tid & 15;      // 0..15 -> 4-col group (x2 halves)

    float acc[4][8];
    #pragma unroll
    for (int i = 0; i < 4; i++)
        #pragma unroll
        for (int j = 0; j < 8; j++) acc[i][j] = 0.0f;

    for (int kc = 0; kc < 128; kc += 16) {
        #pragma unroll
        for (int i = 0; i < 4; i++) {
            int idx = tid + i * 256;
            int r = idx >> 4, kk = idx & 15;
            int row = row0 + r;
            As[kk * AST + r] = (row < M) ? A[(size_t)row * 128 + kc + kk] : 0.0f;
        }
        #pragma unroll
        for (int i = 0; i < 8; i++) {
            int idx = tid + i * 256;
            int kk = idx >> 7, d = idx & 127;
            Bs[kk * 128 + d] = B[(size_t)(kc + kk) * 128 + d];
        }
        __syncthreads();
        #pragma unroll
        for (int kk = 0; kk < 16; kk++) {
            float4 a0 = *(const float4*)&As[kk * AST + ty * 4];
            float4 b0 = *(const float4*)&Bs[kk * 128 + tx * 4];
            float4 b1 = *(const float4*)&Bs[kk * 128 + 64 + tx * 4];
            float av[4] = {a0.x, a0.y, a0.z, a0.w};
            float bv[8] = {b0.x, b0.y, b0.z, b0.w, b1.x, b1.y, b1.z, b1.w};
            #pragma unroll
            for (int i = 0; i < 4; i++)
                #pragma unroll
                for (int j = 0; j < 8; j++) acc[i][j] += av[i] * bv[j];
        }
        __syncthreads();
    }

    if (z == 0) {
        #pragma unroll
        for (int i = 0; i < 4; i++) {
            int row = row0 + ty * 4 + i;
            if (row < M) {
                *(float4*)&d_h[(size_t)row * 128 + tx * 4] =
                    make_float4(acc[i][0], acc[i][1], acc[i][2], acc[i][3]);
                *(float4*)&d_h[(size_t)row * 128 + 64 + tx * 4] =
                    make_float4(acc[i][4], acc[i][5], acc[i][6], acc[i][7]);
            }
        }
    } else {
        // transposed bf16 hi/lo write: WcT[g][d][c], c = Wc row, d = Wc col
        #pragma unroll
        for (int i = 0; i < 4; i++) {
            int c = row0 + ty * 4 + i;
            #pragma unroll
            for (int j = 0; j < 8; j++) {
                int d = (j < 4) ? (tx * 4 + j) : (64 + tx * 4 + (j - 4));
                float v = acc[i][j] * scale;
                __nv_bfloat16 hv = __float2bfloat16_rn(v);
                float lv = v - __bfloat162float(hv);
                size_t o = ((size_t)g * 128 + d) * 128 + c;
                d_WcT_hi[o] = hv;
                d_WcT_lo[o] = __float2bfloat16_rn(lv);
            }
        }
    }
}

// Fallback hist (only if the fused grid had no helper blocks)
__global__ void hist_kernel(const int* __restrict__ recv, int E) {
    int i = blockIdx.x * blockDim.x + threadIdx.x;
    if (i < E) atomicAdd(&d_counts[recv[i]], 1);
}

// ---------------------------------------------------------------------------
// block 0: warp-shuffle scan of d_counts -> d_offsets / d_cursor, then
//          RE-ZEROES d_counts (keeps the zero invariant across graph replays)
// block 1: group nodes by element; tile prefix (64-row tiles); reset counter
// ---------------------------------------------------------------------------
__global__ void scan_elem_kernel(const int* __restrict__ node_elem, int N, int NE) {
    int tid = threadIdx.x;

    if (blockIdx.x == 1) {
        __shared__ int scnt[NE_MAX];
        if (tid < NE) scnt[tid] = 0;
        __syncthreads();
        for (int i = tid; i < N; i += blockDim.x) atomicAdd(&scnt[node_elem[i]], 1);
        __syncthreads();
        if (tid == 0) {
            int run = 0;
            for (int e = 0; e < NE; e++) { d_elem_off[e] = run; d_elem_cur[e] = run; run += scnt[e]; }
            d_elem_off[NE] = run;
            int tp = 0;
            for (int g = 0; g < NE * 4; g++) {
                int l = g & 3;
                int rows = scnt[g >> 2] * (2 * l + 1);
                d_tile_off[g] = tp;
                tp += (rows + 63) >> 6;     // 64-row tiles
            }
            d_tile_off[NE * 4] = tp;
            d_tile_ctr = 0;
        }
        __syncthreads();
        for (int i = tid; i < N; i += blockDim.x) {
            int pos = atomicAdd(&d_elem_cur[node_elem[i]], 1);
            d_node_by_elem[pos] = i;
        }
        return;
    }

    // block 0: scan (1024 threads x 6 elems = 6144 >= N_MAX)
    __shared__ int wtot[32];
    const int PER = 6;
    int lane = tid & 31, w = tid >> 5;
    int base = tid * PER;
    int cnt[PER];
    int run = 0;
    #pragma unroll
    for (int i = 0; i < PER; i++) {
        cnt[i] = (base + i < N) ? d_counts[base + i] : 0;
        run += cnt[i];
    }
    int ws = run;
    #pragma unroll
    for (int o = 1; o < 32; o <<= 1) {
        int t = __shfl_up_sync(0xffffffffu, ws, o);
        if (lane >= o) ws += t;
    }
    if (lane == 31) wtot[w] = ws;
    __syncthreads();
    if (w == 0) {
        int v = wtot[lane];
        #pragma unroll
        for (int o = 1; o < 32; o <<= 1) {
            int t = __shfl_up_sync(0xffffffffu, v, o);
            if (lane >= o) v += t;
        }
        wtot[lane] = v;
    }
    __syncthreads();
    int acc = (w ? wtot[w - 1] : 0) + (ws - run);
    if (tid == 0) d_offsets[0] = 0;
    #pragma unroll
    for (int i = 0; i < PER; i++) {
        int idx = base + i;
        if (idx < N) {
            d_cursor[idx] = acc;
            acc += cnt[i];
            d_offsets[idx + 1] = acc;
            d_counts[idx] = 0;     // restore zero invariant for next replay
        }
    }
}

__global__ void scatter_kernel(const int* __restrict__ recv, int E) {
    int i = blockIdx.x * blockDim.x + threadIdx.x;
    if (i < E) {
        int pos = atomicAdd(&d_cursor[recv[i]], 1);
        d_sorted[pos] = i;
    }
}

// ---------------------------------------------------------------------------
// Edge accumulation (R8 structure, measured best): one CTA per node, 256
// threads. Thread = (channel c = tid&127, parity par = tid>>7), 16 lm accs
// per thread, depth-2 register pipeline, combined via smem. Epilogue writes
// msg as bf16 hi/lo. l_of_lm: [0, 1,1,1, 2,2,2,2,2, 3,3,3,3,3,3,3]
// ---------------------------------------------------------------------------
__global__ __launch_bounds__(256) void edge_accum_kernel(
    const float* __restrict__ edge_attrs,   // [E,16]
    const float* __restrict__ edge_feats,   // [E,4,128]
    const int*   __restrict__ sender)       // [E]
{
    int n = blockIdx.x;
    int tid = threadIdx.x;
    int c = tid & 127;
    int par = tid >> 7;

    __shared__ float s_attr[32][16];
    __shared__ int   s_e[32];
    __shared__ int   s_send[32];
    __shared__ float s_part[16][128];

    float acc[16];
    #pragma unroll
    for (int i = 0; i < 16; i++) acc[i] = 0.0f;

    int beg = d_offsets[n];
    int end = d_offsets[n + 1];

    for (int base = beg; base < end; base += 32) {
        int m = end - base;
        if (m > 32) m = 32;
        if (tid < m) {
            int ee = d_sorted[base + tid];
            s_e[tid] = ee;
            s_send[tid] = sender[ee];
        }
        for (int i = tid; i < m * 16; i += 256) {
            int j = i >> 4;
            s_attr[j][i & 15] = __ldcs(&edge_attrs[(size_t)d_sorted[base + j] * 16 + (i & 15)]);
        }
        __syncthreads();

        int j = par;
        float A0[5] = {0.f, 0.f, 0.f, 0.f, 0.f};
        float A1[5] = {0.f, 0.f, 0.f, 0.f, 0.f};
        if (j < m) {
            const float* efp = edge_feats + (size_t)s_e[j] * 512;
            A0[0] = __ldcs(efp + c);       A0[1] = __ldcs(efp + 128 + c);
            A0[2] = __ldcs(efp + 256 + c); A0[3] = __ldcs(efp + 384 + c);
            A0[4] = d_h[(size_t)s_send[j] * 128 + c];
        }
        if (j + 2 < m) {
            const float* efp = edge_feats + (size_t)s_e[j + 2] * 512;
            A1[0] = __ldcs(efp + c);       A1[1] = __ldcs(efp + 128 + c);
            A1[2] = __ldcs(efp + 256 + c); A1[3] = __ldcs(efp + 384 + c);
            A1[4] = d_h[(size_t)s_send[j + 2] * 128 + c];
        }
        while (j < m) {
            float A2[5] = {0.f, 0.f, 0.f, 0.f, 0.f};
            if (j + 4 < m) {
                const float* efp = edge_feats + (size_t)s_e[j + 4] * 512;
                A2[0] = __ldcs(efp + c);       A2[1] = __ldcs(efp + 128 + c);
                A2[2] = __ldcs(efp + 256 + c); A2[3] = __ldcs(efp + 384 + c);
                A2[4] = d_h[(size_t)s_send[j + 4] * 128 + c];
            }
            const float* at = s_attr[j];
            float hs = A0[4];
            float p0 = hs * A0[0], p1 = hs * A0[1], p2 = hs * A0[2], p3 = hs * A0[3];
            acc[0]  += p0 * at[0];
            acc[1]  += p1 * at[1];
            acc[2]  += p1 * at[2];
            acc[3]  += p1 * at[3];
            acc[4]  += p2 * at[4];
            acc[5]  += p2 * at[5];
            acc[6]  += p2 * at[6];
            acc[7]  += p2 * at[7];
            acc[8]  += p2 * at[8];
            acc[9]  += p3 * at[9];
            acc[10] += p3 * at[10];
            acc[11] += p3 * at[11];
            acc[12] += p3 * at[12];
            acc[13] += p3 * at[13];
            acc[14] += p3 * at[14];
            acc[15] += p3 * at[15];
            #pragma unroll
            for (int q = 0; q < 5; q++) { A0[q] = A1[q]; A1[q] = A2[q]; }
            j += 2;
        }
        __syncthreads();
    }

    if (par) {
        #pragma unroll
        for (int lm = 0; lm < 16; lm++) s_part[lm][c] = acc[lm];
    }
    __syncthreads();
    if (!par) {
        size_t ob = (size_t)n * 2048 + c;
        #pragma unroll
        for (int lm = 0; lm < 16; lm++) {
            float v = acc[lm] + s_part[lm][c];
            __nv_bfloat16 hv = __float2bfloat16_rn(v);
            float lv = v - __bfloat162float(hv);
            d_msg_hi[ob + (size_t)lm * 128] = hv;
            d_msg_lo[ob + (size_t)lm * 128] = __float2bfloat16_rn(lv);
        }
    }
}

// ---------------------------------------------------------------------------
// Output GEMM via mma.sync bf16 (HMMA), hi/lo compensated (hh + hl + lh).
// Static contiguous tile ranges per CTA (148 CTAs; tiles uniform cost).
// Software pipeline: A(t+1) cp.async issued before compute(t) using node ids
// LDG'd at t-1 into registers (each fill thread self-sufficient -> no smem
// round trip); wait lands after epilogue(t). B refilled only on group change
// (rare with contiguous ranges). Smem: A double buffer + B = 139 KB, 1 CTA/SM.
// Tile = 64 rows x 128 cols x K=128; 8 warps, warp tile 32x32.
// ---------------------------------------------------------------------------
#define ROWP 136
#define AHALF (64 * ROWP * 2)                 // 17408 (A hi or lo)
#define ABUF  (2 * AHALF)                     // 34816 per A buffer
#define BHALF (128 * ROWP * 2)                // 34816
#define DSMEM_BYTES (2 * ABUF + 2 * BHALF)    // 139264

__global__ __launch_bounds__(256) void out_gemm_mma(float* __restrict__ out, int NE)
{
    extern __shared__ __nv_bfloat16 smb[];

    __shared__ int s_off[2][64];
    __shared__ int s_toff[NG_MAX + 1];
    __shared__ int s_eoff[NE_MAX + 1];

    int tid = threadIdx.x, wid = tid >> 5, lid = tid & 31;
    int NG = NE * 4;
    if (tid <= NG) s_toff[tid] = d_tile_off[tid];
    if (tid <= NE) s_eoff[tid] = d_elem_off[tid];
    __syncthreads();
    int ntiles = s_toff[NG];
    int G = gridDim.x;
    int start = (int)(((long)blockIdx.x * ntiles) / G);
    int endt  = (int)(((long)(blockIdx.x + 1) * ntiles) / G);
    if (start >= endt) return;

    int wm0 = (wid & 1) * 32;
    int wn0 = (wid >> 1) * 32;

    // ldmatrix lane geometry (byte offsets within a buffer)
    int a_row0 = wm0 + ((lid >> 3) & 1) * 8 + (lid & 7);
    int a_kadd = ((lid >> 4) & 1) * 8;
    uint32_t aoff[2];
    #pragma unroll
    for (int mt = 0; mt < 2; mt++)
        aoff[mt] = (uint32_t)(((a_row0 + mt * 16) * ROWP + a_kadd) * 2);
    int b_row0 = wn0 + ((lid >> 4) & 1) * 8 + (lid & 7);
    int b_kadd = ((lid >> 3) & 1) * 8;
    uint32_t boff[2];
    #pragma unroll
    for (int p = 0; p < 2; p++)
        boff[p] = (uint32_t)(((b_row0 + p * 16) * ROWP + b_kadd) * 2);

    uint32_t base = smem_u32(smb);
    uint32_t sB_hi = base + 2 * ABUF;
    uint32_t sB_lo = sB_hi + BHALF;
    char* smc = (char*)smb;

    // tile info from smem prefix tables
    auto tinfo = [&](int t, int& g, int& l, int& tw, int& cbeg, int& rows, int& trow) {
        g = 0;
        while (s_toff[g + 1] <= t) g++;
        l = g & 3; tw = 2 * l + 1;
        cbeg = s_eoff[g >> 2];
        rows = (s_eoff[(g >> 2) + 1] - cbeg) * tw;
        trow = (t - s_toff[g]) * 64;
    };

    // fill-thread geometry: per q in 0..3: i = tid + q*256, r = i>>4, w = i&15
    // issue A fill for tile (given per-q node ids in regs) into buffer `buf`
    auto issueA = [&](int buf, int l, int tw, int rows, int trow,
                      const int* nid, int so_slot) {
        uint32_t abase = base + (uint32_t)buf * ABUF;
        #pragma unroll
        for (int q = 0; q < 4; q++) {
            int i = tid + q * 256;
            int r = i >> 4, w = i & 15;
            int rr = trow + r;
            int off = -1;
            if (rr < rows) off = (nid[q] * 16 + l * l + rr % tw) * 128;
            if (w == 0) s_off[so_slot][r] = off;
            uint32_t d = (uint32_t)((r * ROWP + w * 8) * 2);
            if (off >= 0) {
                CP16(abase + d, d_msg_hi + (size_t)off + w * 8);
                CP16(abase + AHALF + d, d_msg_lo + (size_t)off + w * 8);
            } else {
                size_t eb = (size_t)buf * ABUF + d;
                *(uint4*)(smc + eb) = make_uint4(0, 0, 0, 0);
                *(uint4*)(smc + eb + AHALF) = make_uint4(0, 0, 0, 0);
            }
        }
    };

    // load node ids for tile t into regs (4 per thread, one per q)
    auto loadNid = [&](int t, int* nid) {
        int g, l, tw, cbeg, rows, trow;
        tinfo(t, g, l, tw, cbeg, rows, trow);
        #pragma unroll
        for (int q = 0; q < 4; q++) {
            int r = (tid + q * 256) >> 4;
            int rr = trow + r;
            nid[q] = (rr < rows) ? d_node_by_elem[cbeg + rr / tw] : 0;
        }
    };

    auto fillB = [&](int g) {
        #pragma unroll
        for (int q = 0; q < 8; q++) {
            int i = tid + q * 256;
            int r = i >> 4, w = i & 15;
            uint32_t d = (uint32_t)((r * ROWP + w * 8) * 2);
            CP16(sB_hi + d, d_WcT_hi + ((size_t)g * 128 + r) * 128 + w * 8);
            CP16(sB_lo + d, d_WcT_lo + ((size_t)g * 128 + r) * 128 + w * 8);
        }
    };

    // ---- prologue: tile `start` synchronously ----
    int nid[4];
    int gcur, l0, tw0, cb0, rw0, tr0;
    tinfo(start, gcur, l0, tw0, cb0, rw0, tr0);
    loadNid(start, nid);                    // exposed LDG wait (once per CTA)
    issueA(0, l0, tw0, rw0, tr0, nid, 0);
    fillB(gcur);
    CP_COMMIT();
    if (start + 1 < endt) loadNid(start + 1, nid);
    cp_wait<0>();
    __syncthreads();

    int cur = 0;

    for (int t = start; t < endt; t++) {
        bool hn = (t + 1 < endt);
        int gn = gcur;
        if (hn) {
            int l2, tw2, cb2, rw2, tr2;
            tinfo(t + 1, gn, l2, tw2, cb2, rw2, tr2);
            issueA(1 - cur, l2, tw2, rw2, tr2, nid, 1 - cur);
            CP_COMMIT();
            if (t + 2 < endt) loadNid(t + 2, nid);
        }

        // ---- compute tile t from buffer cur ----
        uint32_t sA_hi = base + (uint32_t)cur * ABUF;
        uint32_t sA_lo = sA_hi + AHALF;

        float acc[2][4][4];
        #pragma unroll
        for (int mt = 0; mt < 2; mt++)
            #pragma unroll
            for (int nt = 0; nt < 4; nt++)
                #pragma unroll
                for (int q = 0; q < 4; q++) acc[mt][nt][q] = 0.0f;

        #pragma unroll
        for (int ks = 0; ks < 8; ks++) {
            uint32_t kb = (uint32_t)(ks * 16 * 2);
            uint32_t ah[2][4], al[2][4];
            #pragma unroll
            for (int mt = 0; mt < 2; mt++) {
                LDSM4(ah[mt][0], ah[mt][1], ah[mt][2], ah[mt][3], sA_hi + aoff[mt] + kb);
                LDSM4(al[mt][0], al[mt][1], al[mt][2], al[mt][3], sA_lo + aoff[mt] + kb);
            }
            uint32_t bh[4][2], bl[4][2];
            #pragma unroll
            for (int p = 0; p < 2; p++) {
                uint32_t r0, r1, r2, r3;
                LDSM4(r0, r1, r2, r3, sB_hi + boff[p] + kb);
                bh[2 * p][0] = r0; bh[2 * p][1] = r1;
                bh[2 * p + 1][0] = r2; bh[2 * p + 1][1] = r3;
                LDSM4(r0, r1, r2, r3, sB_lo + boff[p] + kb);
                bl[2 * p][0] = r0; bl[2 * p][1] = r1;
                bl[2 * p + 1][0] = r2; bl[2 * p + 1][1] = r3;
            }
            #pragma unroll
            for (int mt = 0; mt < 2; mt++)
                #pragma unroll
                for (int nt = 0; nt < 4; nt++) {
                    MMA16816(acc[mt][nt], ah[mt], bh[nt]);   // hi*hi
                    MMA16816(acc[mt][nt], ah[mt], bl[nt]);   // hi*lo
                    MMA16816(acc[mt][nt], al[mt], bh[nt]);   // lo*hi
                }
        }

        // ---- epilogue tile t ----
        #pragma unroll
        for (int mt = 0; mt < 2; mt++) {
            int r0 = wm0 + mt * 16 + (lid >> 2);
            int off0 = s_off[cur][r0];
            int off1 = s_off[cur][r0 + 8];
            #pragma unroll
            for (int nt = 0; nt < 4; nt++) {
                int col = wn0 + nt * 8 + (lid & 3) * 2;
                if (off0 >= 0)
                    *(float2*)&out[(size_t)off0 + col] =
                        make_float2(acc[mt][nt][0], acc[mt][nt][1]);
                if (off1 >= 0)
                    *(float2*)&out[(size_t)off1 + col] =
                        make_float2(acc[mt][nt][2], acc[mt][nt][3]);
            }
        }

        if (hn) {
            cp_wait<0>();        // A(t+1) landed
            __syncthreads();     // fills + s_off visible; buffers safe to swap
            if (gn != gcur) {    // rare: group boundary inside this CTA's range
                fillB(gn);
                CP_COMMIT();
                cp_wait<0>();
                __syncthreads();
                gcur = gn;
            }
            cur ^= 1;
        }
    }
}

// ---------------------------------------------------------------------------
// Launch
// ---------------------------------------------------------------------------
extern "C" void kernel_launch(void* const* d_in, const int* in_sizes, int n_in,
                              void* d_out, int out_size)
{
    const float* node_feats = (const float*)d_in[0];   // [N,128]
    const float* edge_attrs = (const float*)d_in[1];   // [E,16]
    const float* edge_feats = (const float*)d_in[2];   // [E,512]
    const float* W_up       = (const float*)d_in[3];   // [128,128]
    const float* W_lin      = (const float*)d_in[4];   // [4,128,128]
    const float* W_skip     = (const float*)d_in[5];   // [NE,4,128,128]
    const int*   edge_index = (const int*)d_in[6];     // [2,E]
    const int*   node_elem  = (const int*)d_in[7];     // [N]

    int N  = in_sizes[7];
    int E  = in_sizes[1] / 16;
    int NE = in_sizes[5] / (4 * 128 * 128);

    const int* sender = edge_index;
    const int* recv   = edge_index + E;

    int gx = (N + 63) / 64;

    // immediate host-side attribute set (not stream-ordered; capture-safe)
    cudaFuncSetAttribute(out_gemm_mma,
                         cudaFuncAttributeMaxDynamicSharedMemorySize, DSMEM_BYTES);

    // 0. h GEMM + WcT bf16 hi/lo + receiver histogram (counts pre-zeroed:
    //    initial load zeros + scan re-zeroes each replay)
    gemm_fused_kernel<<<dim3(gx, 1, 1 + NE * 4), 256>>>(
        node_feats, W_up, W_lin, W_skip, recv, N, E, NE);
    if (gx < 3)   // degenerate: no helper blocks existed
        hist_kernel<<<(E + 255) / 256, 256>>>(recv, E);

    // 1. scan (+ re-zero counts) + element grouping + tile prefix (64-row)
    scan_elem_kernel<<<2, 1024>>>(node_elem, N, NE);

    // 2. counting-sort scatter
    scatter_kernel<<<(E + 255) / 256, 256>>>(recv, E);

    // 3. per-node edge accumulation -> msg (bf16 hi/lo)
    edge_accum_kernel<<<N, 256>>>(edge_attrs, edge_feats, sender);

    // 4. output GEMM on tensor cores (pipelined, static tile ranges)
    out_gemm_mma<<<148, 256, DSMEM_BYTES>>>((float*)d_out, NE);
}

// round 15
// speedup vs baseline: 1.1067x; 1.1067x over previous
#include <cuda_runtime.h>
#include <cuda_bf16.h>
#include <cstdint>

// ---------------------------------------------------------------------------
// MACE invariant message passing:
//   h   = node_feats @ W_up
//   m   = h[sender] * edge_attrs * edge_feats[l_of_lm]   (per edge)
//   msg = segment_sum over receiver  (stored as bf16 hi/lo)
//   out = msg @ ( W_lin[l] @ W_skip[elem,l] / 16 )       (grouped by element)
// Output GEMM: warp-level mma.sync bf16 (HMMA) with hi/lo compensation.
// ---------------------------------------------------------------------------

typedef unsigned long long u64;

#define N_MAX 6144
#define E_MAX 131072
#define NE_MAX 16
#define NG_MAX (NE_MAX * 4)
#define AST 68    // As row stride (floats) in the scalar GEMM (BM=64 + pad)

// Static device scratch (allocation-free per harness rules)
__device__ float d_h[(size_t)N_MAX * 128];
__device__ __nv_bfloat16 d_msg_hi[(size_t)N_MAX * 16 * 128];
__device__ __nv_bfloat16 d_msg_lo[(size_t)N_MAX * 16 * 128];
__device__ __nv_bfloat16 d_WcT_hi[(size_t)NG_MAX * 128 * 128];
__device__ __nv_bfloat16 d_WcT_lo[(size_t)NG_MAX * 128 * 128];
__device__ int   d_sorted[E_MAX];
__device__ int   d_counts[N_MAX];          // zero-init; scan re-zeroes after use
__device__ int   d_offsets[N_MAX + 1];
__device__ int   d_cursor[N_MAX];
__device__ int   d_node_by_elem[N_MAX];
__device__ int   d_elem_off[NE_MAX + 1];
__device__ int   d_elem_cur[NE_MAX];
__device__ int   d_tile_off[NG_MAX + 1];
__device__ int   d_tile_ctr;

// --------------------------- helpers ---------------------------------------
__device__ __forceinline__ uint32_t smem_u32(const void* p) {
    uint32_t a;
    asm("{ .reg .u64 t; cvta.to.shared.u64 t, %1; cvt.u32.u64 %0, t; }"
        : "=r"(a) : "l"(p));
    return a;
}

#define CP16(dst, src) \
    asm volatile("cp.async.cg.shared.global [%0], [%1], 16;" \
        :: "r"(dst), "l"(src) : "memory")
#define CP_COMMIT() asm volatile("cp.async.commit_group;" ::: "memory")
template <int W>
__device__ __forceinline__ void cp_wait() {
    asm volatile("cp.async.wait_group %0;" :: "n"(W) : "memory");
}

#define LDSM4(r0, r1, r2, r3, addr) \
    asm volatile("ldmatrix.sync.aligned.m8n8.x4.shared.b16 {%0,%1,%2,%3}, [%4];" \
        : "=r"(r0), "=r"(r1), "=r"(r2), "=r"(r3) : "r"(addr))

#define MMA16816(c, a, b) \
    asm volatile("mma.sync.aligned.m16n8k16.row.col.f32.bf16.bf16.f32 " \
        "{%0,%1,%2,%3}, {%4,%5,%6,%7}, {%8,%9}, {%0,%1,%2,%3};" \
        : "+f"((c)[0]), "+f"((c)[1]), "+f"((c)[2]), "+f"((c)[3]) \
        : "r"((a)[0]), "r"((a)[1]), "r"((a)[2]), "r"((a)[3]), \
          "r"((b)[0]), "r"((b)[1]))

// ---------------------------------------------------------------------------
// Fused GEMM kernel (scalar fp32, BM=64, BN=128, BK=16, acc 4x8 -> no spills):
//   z == 0          : h = node_feats @ W_up          (tiles over blockIdx.x)
//   z >= 1, x <= 1  : WcT[g] rows x*64..+63 = transpose(W_lin[l] @ W_skip[g]/16)
//   z >= 1, x >= 2  : helper blocks run the receiver histogram
// ---------------------------------------------------------------------------
__global__ __launch_bounds__(256) void gemm_fused_kernel(
    const float* __restrict__ node_feats,
    const float* __restrict__ W_up,
    const float* __restrict__ W_lin,
    const float* __restrict__ W_skip,
    const int*   __restrict__ recv,
    int N, int E, int NE)
{
    const float* A;
    const float* B;
    int M;
    float scale;
    int z = blockIdx.z;
    int g = z - 1;
    int row0;

    if (z == 0) {
        A = node_feats; B = W_up; M = N; scale = 1.0f;
        row0 = blockIdx.x * 64;
    } else {
        if (blockIdx.x >= 2) {
            int nb  = gridDim.x - 2;
            int id  = (z - 1) * nb + (blockIdx.x - 2);
            int tot = (int)(gridDim.z - 1) * nb;
            for (int i = id * 256 + threadIdx.x; i < E; i += tot * 256)
                atomicAdd(&d_counts[recv[i]], 1);
            return;
        }
        int l = g & 3;
        A = W_lin  + (size_t)l * 16384;
        B = W_skip + (size_t)g * 16384;
        M = 128; scale = 1.0f / 16.0f;
        row0 = blockIdx.x * 64;
    }

    __shared__ float As[16 * AST];
    __shared__ float Bs[16 * 128];

    int tid = threadIdx.x;
    int ty = tid >> 4;      // 0..15 -> 4-row group
    int tx = tid & 15;      // 0..15 -> 4-col group (x2 halves)

    float acc[4][8];
    #pragma unroll
    for (int i = 0; i < 4; i++)
        #pragma unroll
        for (int j = 0; j < 8; j++) acc[i][j] = 0.0f;

    for (int kc = 0; kc < 128; kc += 16) {
        #pragma unroll
        for (int i = 0; i < 4; i++) {
            int idx = tid + i * 256;
            int r = idx >> 4, kk = idx & 15;
            int row = row0 + r;
            As[kk * AST + r] = (row < M) ? A[(size_t)row * 128 + kc + kk] : 0.0f;
        }
        #pragma unroll
        for (int i = 0; i < 8; i++) {
            int idx = tid + i * 256;
            int kk = idx >> 7, d = idx & 127;
            Bs[kk * 128 + d] = B[(size_t)(kc + kk) * 128 + d];
        }
        __syncthreads();
        #pragma unroll
        for (int kk = 0; kk < 16; kk++) {
            float4 a0 = *(const float4*)&As[kk * AST + ty * 4];
            float4 b0 = *(const float4*)&Bs[kk * 128 + tx * 4];
            float4 b1 = *(const float4*)&Bs[kk * 128 + 64 + tx * 4];
            float av[4] = {a0.x, a0.y, a0.z, a0.w};
            float bv[8] = {b0.x, b0.y, b0.z, b0.w, b1.x, b1.y, b1.z, b1.w};
            #pragma unroll
            for (int i = 0; i < 4; i++)
                #pragma unroll
                for (int j = 0; j < 8; j++) acc[i][j] += av[i] * bv[j];
        }
        __syncthreads();
    }

    if (z == 0) {
        #pragma unroll
        for (int i = 0; i < 4; i++) {
            int row = row0 + ty * 4 + i;
            if (row < M) {
                *(float4*)&d_h[(size_t)row * 128 + tx * 4] =
                    make_float4(acc[i][0], acc[i][1], acc[i][2], acc[i][3]);
                *(float4*)&d_h[(size_t)row * 128 + 64 + tx * 4] =
                    make_float4(acc[i][4], acc[i][5], acc[i][6], acc[i][7]);
            }
        }
    } else {
        // transposed bf16 hi/lo write: WcT[g][d][c], c = Wc row, d = Wc col
        #pragma unroll
        for (int i = 0; i < 4; i++) {
            int c = row0 + ty * 4 + i;
            #pragma unroll
            for (int j = 0; j < 8; j++) {
                int d = (j < 4) ? (tx * 4 + j) : (64 + tx * 4 + (j - 4));
                float v = acc[i][j] * scale;
                __nv_bfloat16 hv = __float2bfloat16_rn(v);
                float lv = v - __bfloat162float(hv);
                size_t o = ((size_t)g * 128 + d) * 128 + c;
                d_WcT_hi[o] = hv;
                d_WcT_lo[o] = __float2bfloat16_rn(lv);
            }
        }
    }
}

// Fallback hist (only if the fused grid had no helper blocks)
__global__ void hist_kernel(const int* __restrict__ recv, int E) {
    int i = blockIdx.x * blockDim.x + threadIdx.x;
    if (i < E) atomicAdd(&d_counts[recv[i]], 1);
}

// ---------------------------------------------------------------------------
// block 0: warp-shuffle scan of d_counts -> d_offsets / d_cursor, then
//          RE-ZEROES d_counts (keeps the zero invariant across graph replays)
// block 1: group nodes by element; tile prefix (64-row tiles); reset counter
// ---------------------------------------------------------------------------
__global__ void scan_elem_kernel(const int* __restrict__ node_elem, int N, int NE) {
    int tid = threadIdx.x;

    if (blockIdx.x == 1) {
        __shared__ int scnt[NE_MAX];
        if (tid < NE) scnt[tid] = 0;
        __syncthreads();
        for (int i = tid; i < N; i += blockDim.x) atomicAdd(&scnt[node_elem[i]], 1);
        __syncthreads();
        if (tid == 0) {
            int run = 0;
            for (int e = 0; e < NE; e++) { d_elem_off[e] = run; d_elem_cur[e] = run; run += scnt[e]; }
            d_elem_off[NE] = run;
            int tp = 0;
            for (int g = 0; g < NE * 4; g++) {
                int l = g & 3;
                int rows = scnt[g >> 2] * (2 * l + 1);
                d_tile_off[g] = tp;
                tp += (rows + 63) >> 6;     // 64-row tiles
            }
            d_tile_off[NE * 4] = tp;
            d_tile_ctr = 0;
        }
        __syncthreads();
        for (int i = tid; i < N; i += blockDim.x) {
            int pos = atomicAdd(&d_elem_cur[node_elem[i]], 1);
            d_node_by_elem[pos] = i;
        }
        return;
    }

    // block 0: scan (1024 threads x 6 elems = 6144 >= N_MAX)
    __shared__ int wtot[32];
    const int PER = 6;
    int lane = tid & 31, w = tid >> 5;
    int base = tid * PER;
    int cnt[PER];
    int run = 0;
    #pragma unroll
    for (int i = 0; i < PER; i++) {
        cnt[i] = (base + i < N) ? d_counts[base + i] : 0;
        run += cnt[i];
    }
    int ws = run;
    #pragma unroll
    for (int o = 1; o < 32; o <<= 1) {
        int t = __shfl_up_sync(0xffffffffu, ws, o);
        if (lane >= o) ws += t;
    }
    if (lane == 31) wtot[w] = ws;
    __syncthreads();
    if (w == 0) {
        int v = wtot[lane];
        #pragma unroll
        for (int o = 1; o < 32; o <<= 1) {
            int t = __shfl_up_sync(0xffffffffu, v, o);
            if (lane >= o) v += t;
        }
        wtot[lane] = v;
    }
    __syncthreads();
    int acc = (w ? wtot[w - 1] : 0) + (ws - run);
    if (tid == 0) d_offsets[0] = 0;
    #pragma unroll
    for (int i = 0; i < PER; i++) {
        int idx = base + i;
        if (idx < N) {
            d_cursor[idx] = acc;
            acc += cnt[i];
            d_offsets[idx + 1] = acc;
            d_counts[idx] = 0;     // restore zero invariant for next replay
        }
    }
}

__global__ void scatter_kernel(const int* __restrict__ recv, int E) {
    int i = blockIdx.x * blockDim.x + threadIdx.x;
    if (i < E) {
        int pos = atomicAdd(&d_cursor[recv[i]], 1);
        d_sorted[pos] = i;
    }
}

// ---------------------------------------------------------------------------
// Edge accumulation (R8 structure, measured best): one CTA per node, 256
// threads. Thread = (channel c = tid&127, parity par = tid>>7), 16 lm accs
// per thread, depth-2 register pipeline, combined via smem. h through the
// read-only (L1) path, edge data streamed. Epilogue writes msg as bf16 hi/lo.
// l_of_lm: [0, 1,1,1, 2,2,2,2,2, 3,3,3,3,3,3,3]
// ---------------------------------------------------------------------------
__global__ __launch_bounds__(256) void edge_accum_kernel(
    const float* __restrict__ edge_attrs,   // [E,16]
    const float* __restrict__ edge_feats,   // [E,4,128]
    const int*   __restrict__ sender)       // [E]
{
    int n = blockIdx.x;
    int tid = threadIdx.x;
    int c = tid & 127;
    int par = tid >> 7;

    __shared__ float s_attr[32][16];
    __shared__ int   s_e[32];
    __shared__ int   s_send[32];
    __shared__ float s_part[16][128];

    float acc[16];
    #pragma unroll
    for (int i = 0; i < 16; i++) acc[i] = 0.0f;

    int beg = d_offsets[n];
    int end = d_offsets[n + 1];

    for (int base = beg; base < end; base += 32) {
        int m = end - base;
        if (m > 32) m = 32;
        if (tid < m) {
            int ee = d_sorted[base + tid];
            s_e[tid] = ee;
            s_send[tid] = sender[ee];
        }
        for (int i = tid; i < m * 16; i += 256) {
            int j = i >> 4;
            s_attr[j][i & 15] = __ldcs(&edge_attrs[(size_t)d_sorted[base + j] * 16 + (i & 15)]);
        }
        __syncthreads();

        int j = par;
        float A0[5] = {0.f, 0.f, 0.f, 0.f, 0.f};
        float A1[5] = {0.f, 0.f, 0.f, 0.f, 0.f};
        if (j < m) {
            const float* efp = edge_feats + (size_t)s_e[j] * 512;
            A0[0] = __ldcs(efp + c);       A0[1] = __ldcs(efp + 128 + c);
            A0[2] = __ldcs(efp + 256 + c); A0[3] = __ldcs(efp + 384 + c);
            A0[4] = __ldg(&d_h[(size_t)s_send[j] * 128 + c]);
        }
        if (j + 2 < m) {
            const float* efp = edge_feats + (size_t)s_e[j + 2] * 512;
            A1[0] = __ldcs(efp + c);       A1[1] = __ldcs(efp + 128 + c);
            A1[2] = __ldcs(efp + 256 + c); A1[3] = __ldcs(efp + 384 + c);
            A1[4] = __ldg(&d_h[(size_t)s_send[j + 2] * 128 + c]);
        }
        while (j < m) {
            float A2[5] = {0.f, 0.f, 0.f, 0.f, 0.f};
            if (j + 4 < m) {
                const float* efp = edge_feats + (size_t)s_e[j + 4] * 512;
                A2[0] = __ldcs(efp + c);       A2[1] = __ldcs(efp + 128 + c);
                A2[2] = __ldcs(efp + 256 + c); A2[3] = __ldcs(efp + 384 + c);
                A2[4] = __ldg(&d_h[(size_t)s_send[j + 4] * 128 + c]);
            }
            const float* at = s_attr[j];
            float hs = A0[4];
            float p0 = hs * A0[0], p1 = hs * A0[1], p2 = hs * A0[2], p3 = hs * A0[3];
            acc[0]  += p0 * at[0];
            acc[1]  += p1 * at[1];
            acc[2]  += p1 * at[2];
            acc[3]  += p1 * at[3];
            acc[4]  += p2 * at[4];
            acc[5]  += p2 * at[5];
            acc[6]  += p2 * at[6];
            acc[7]  += p2 * at[7];
            acc[8]  += p2 * at[8];
            acc[9]  += p3 * at[9];
            acc[10] += p3 * at[10];
            acc[11] += p3 * at[11];
            acc[12] += p3 * at[12];
            acc[13] += p3 * at[13];
            acc[14] += p3 * at[14];
            acc[15] += p3 * at[15];
            #pragma unroll
            for (int q = 0; q < 5; q++) { A0[q] = A1[q]; A1[q] = A2[q]; }
            j += 2;
        }
        __syncthreads();
    }

    if (par) {
        #pragma unroll
        for (int lm = 0; lm < 16; lm++) s_part[lm][c] = acc[lm];
    }
    __syncthreads();
    if (!par) {
        size_t ob = (size_t)n * 2048 + c;
        #pragma unroll
        for (int lm = 0; lm < 16; lm++) {
            float v = acc[lm] + s_part[lm][c];
            __nv_bfloat16 hv = __float2bfloat16_rn(v);
            float lv = v - __bfloat162float(hv);
            d_msg_hi[ob + (size_t)lm * 128] = hv;
            d_msg_lo[ob + (size_t)lm * 128] = __float2bfloat16_rn(lv);
        }
    }
}

// ---------------------------------------------------------------------------
// Output GEMM via mma.sync bf16 (HMMA), hi/lo compensated (hh + hl + lh).
// Persistent PAIRED tile queue (pop 2 tiles per atomic -> second tile almost
// always shares the group, so its 69KB B refill is skipped). BM=64 tiles,
// 102KB smem -> 2 CTAs/SM for cross-CTA overlap (measured best structure).
// Tile = 64 gathered msg rows x 128 cols x K=128; 8 warps, warp tile 32x32.
// ---------------------------------------------------------------------------
#define ROWP 136
#define A_BUF (64 * ROWP * 2)               // 17408
#define B_BUF (128 * ROWP * 2)              // 34816
#define DSMEM_BYTES (2 * A_BUF + 2 * B_BUF) // 104448

__global__ __launch_bounds__(256, 2) void out_gemm_mma(float* __restrict__ out, int NE)
{
    extern __shared__ __nv_bfloat16 smb[];
    __nv_bfloat16* A_hi = smb;
    __nv_bfloat16* A_lo = smb + 64 * ROWP;

    __shared__ int s_off[64];
    __shared__ int s_toff[NG_MAX + 1];
    __shared__ int s_eoff[NE_MAX + 1];
    __shared__ int s_tile;

    int tid = threadIdx.x, wid = tid >> 5, lid = tid & 31;
    int NG = NE * 4;
    if (tid <= NG) s_toff[tid] = d_tile_off[tid];
    if (tid <= NE) s_eoff[tid] = d_elem_off[tid];
    __syncthreads();
    int ntiles = s_toff[NG];

    int wm0 = (wid & 1) * 32;     // warp row base (0/32)
    int wn0 = (wid >> 1) * 32;    // warp col base (0..96)

    // ldmatrix lane geometry (byte offsets within a buffer)
    int a_row0 = wm0 + ((lid >> 3) & 1) * 8 + (lid & 7);
    int a_kadd = ((lid >> 4) & 1) * 8;
    uint32_t aoff[2];
    #pragma unroll
    for (int mt = 0; mt < 2; mt++)
        aoff[mt] = (uint32_t)(((a_row0 + mt * 16) * ROWP + a_kadd) * 2);
    int b_row0 = wn0 + ((lid >> 4) & 1) * 8 + (lid & 7);
    int b_kadd = ((lid >> 3) & 1) * 8;
    uint32_t boff[2];
    #pragma unroll
    for (int p = 0; p < 2; p++)
        boff[p] = (uint32_t)(((b_row0 + p * 16) * ROWP + b_kadd) * 2);

    uint32_t sA_hi = smem_u32(smb);
    uint32_t sA_lo = sA_hi + A_BUF;
    uint32_t sB_hi = sA_hi + 2 * A_BUF;
    uint32_t sB_lo = sA_hi + 2 * A_BUF + B_BUF;

    int g_prev = -1;

    while (true) {
        if (tid == 0) s_tile = atomicAdd(&d_tile_ctr, 2);   // paired pop
        __syncthreads();
        int t0 = s_tile;
        if (t0 >= ntiles) break;
        int t1 = (t0 + 2 < ntiles) ? t0 + 2 : ntiles;

        for (int t = t0; t < t1; t++) {
            int g = 0;
            while (s_toff[g + 1] <= t) g++;
            int l = g & 3, e = g >> 2;
            int tw = 2 * l + 1;
            int cbeg = s_eoff[e];
            int rows = (s_eoff[e + 1] - cbeg) * tw;
            int tile = (t - s_toff[g]) * 64;
            bool fillB = (g != g_prev);
            g_prev = g;

            if (tid < 64) {
                int rr = tile + tid;
                int off = -1;
                if (rr < rows) {
                    int node = d_node_by_elem[cbeg + rr / tw];
                    off = (node * 16 + l * l + rr % tw) * 128;
                }
                s_off[tid] = off;
            }
            __syncthreads();

            // --- fill A via cp.async (64 rows x 16 float4 jobs, 4/thread) ---
            #pragma unroll
            for (int q = 0; q < 4; q++) {
                int i = tid + q * 256;
                int r = i >> 4, w = i & 15;
                int off = s_off[r];
                uint32_t d = (uint32_t)((r * ROWP + w * 8) * 2);
                if (off >= 0) {
                    CP16(sA_hi + d, d_msg_hi + (size_t)off + w * 8);
                    CP16(sA_lo + d, d_msg_lo + (size_t)off + w * 8);
                } else {
                    *(uint4*)(A_hi + r * ROWP + w * 8) = make_uint4(0, 0, 0, 0);
                    *(uint4*)(A_lo + r * ROWP + w * 8) = make_uint4(0, 0, 0, 0);
                }
            }
            // --- fill B via cp.async only when the group changed ---
            if (fillB) {
                #pragma unroll
                for (int q = 0; q < 8; q++) {
                    int i = tid + q * 256;
                    int r = i >> 4, w = i & 15;
                    uint32_t d = (uint32_t)((r * ROWP + w * 8) * 2);
                    CP16(sB_hi + d, d_WcT_hi + ((size_t)g * 128 + r) * 128 + w * 8);
                    CP16(sB_lo + d, d_WcT_lo + ((size_t)g * 128 + r) * 128 + w * 8);
                }
            }
            CP_COMMIT();
            cp_wait<0>();
            __syncthreads();

            // --- compute ---
            float acc[2][4][4];
            #pragma unroll
            for (int mt = 0; mt < 2; mt++)
                #pragma unroll
                for (int nt = 0; nt < 4; nt++)
                    #pragma unroll
                    for (int q = 0; q < 4; q++) acc[mt][nt][q] = 0.0f;

            #pragma unroll
            for (int ks = 0; ks < 8; ks++) {
                uint32_t kb = (uint32_t)(ks * 16 * 2);
                uint32_t ah[2][4], al[2][4];
                #pragma unroll
                for (int mt = 0; mt < 2; mt++) {
                    LDSM4(ah[mt][0], ah[mt][1], ah[mt][2], ah[mt][3], sA_hi + aoff[mt] + kb);
                    LDSM4(al[mt][0], al[mt][1], al[mt][2], al[mt][3], sA_lo + aoff[mt] + kb);
                }
                uint32_t bh[4][2], bl[4][2];
                #pragma unroll
                for (int p = 0; p < 2; p++) {
                    uint32_t r0, r1, r2, r3;
                    LDSM4(r0, r1, r2, r3, sB_hi + boff[p] + kb);
                    bh[2 * p][0] = r0; bh[2 * p][1] = r1;
                    bh[2 * p + 1][0] = r2; bh[2 * p + 1][1] = r3;
                    LDSM4(r0, r1, r2, r3, sB_lo + boff[p] + kb);
                    bl[2 * p][0] = r0; bl[2 * p][1] = r1;
                    bl[2 * p + 1][0] = r2; bl[2 * p + 1][1] = r3;
                }
                #pragma unroll
                for (int mt = 0; mt < 2; mt++)
                    #pragma unroll
                    for (int nt = 0; nt < 4; nt++) {
                        MMA16816(acc[mt][nt], ah[mt], bh[nt]);   // hi*hi
                        MMA16816(acc[mt][nt], ah[mt], bl[nt]);   // hi*lo
                        MMA16816(acc[mt][nt], al[mt], bh[nt]);   // lo*hi
                    }
            }

            // --- epilogue: scatter to out via s_off ---
            #pragma unroll
            for (int mt = 0; mt < 2; mt++) {
                int r0 = wm0 + mt * 16 + (lid >> 2);
                int off0 = s_off[r0];
                int off1 = s_off[r0 + 8];
                #pragma unroll
                for (int nt = 0; nt < 4; nt++) {
                    int col = wn0 + nt * 8 + (lid & 3) * 2;
                    if (off0 >= 0)
                        *(float2*)&out[(size_t)off0 + col] =
                            make_float2(acc[mt][nt][0], acc[mt][nt][1]);
                    if (off1 >= 0)
                        *(float2*)&out[(size_t)off1 + col] =
                            make_float2(acc[mt][nt][2], acc[mt][nt][3]);
                }
            }
            __syncthreads();   // protect smem/s_off before next tile
        }
    }
}

// ---------------------------------------------------------------------------
// Launch
// ---------------------------------------------------------------------------
extern "C" void kernel_launch(void* const* d_in, const int* in_sizes, int n_in,
                              void* d_out, int out_size)
{
    const float* node_feats = (const float*)d_in[0];   // [N,128]
    const float* edge_attrs = (const float*)d_in[1];   // [E,16]
    const float* edge_feats = (const float*)d_in[2];   // [E,512]
    const float* W_up       = (const float*)d_in[3];   // [128,128]
    const float* W_lin      = (const float*)d_in[4];   // [4,128,128]
    const float* W_skip     = (const float*)d_in[5];   // [NE,4,128,128]
    const int*   edge_index = (const int*)d_in[6];     // [2,E]
    const int*   node_elem  = (const int*)d_in[7];     // [N]

    int N  = in_sizes[7];
    int E  = in_sizes[1] / 16;
    int NE = in_sizes[5] / (4 * 128 * 128);

    const int* sender = edge_index;
    const int* recv   = edge_index + E;

    int gx = (N + 63) / 64;

    // immediate host-side attribute set (not stream-ordered; capture-safe)
    cudaFuncSetAttribute(out_gemm_mma,
                         cudaFuncAttributeMaxDynamicSharedMemorySize, DSMEM_BYTES);

    // 0. h GEMM + WcT bf16 hi/lo + receiver histogram (counts pre-zeroed:
    //    initial load zeros + scan re-zeroes each replay)
    gemm_fused_kernel<<<dim3(gx, 1, 1 + NE * 4), 256>>>(
        node_feats, W_up, W_lin, W_skip, recv, N, E, NE);
    if (gx < 3)   // degenerate: no helper blocks existed
        hist_kernel<<<(E + 255) / 256, 256>>>(recv, E);

    // 1. scan (+ re-zero counts) + element grouping + tile prefix (64-row)
    scan_elem_kernel<<<2, 1024>>>(node_elem, N, NE);

    // 2. counting-sort scatter
    scatter_kernel<<<(E + 255) / 256, 256>>>(recv, E);

    // 3. per-node edge accumulation -> msg (bf16 hi/lo)
    edge_accum_kernel<<<N, 256>>>(edge_attrs, edge_feats, sender);

    // 4. output GEMM on tensor cores (paired tile pops, 2 CTAs/SM)
    out_gemm_mma<<<296, 256, DSMEM_BYTES>>>((float*)d_out, NE);
}

// round 16
// speedup vs baseline: 1.4008x; 1.2658x over previous
#include <cuda_runtime.h>
#include <cuda_fp16.h>
#include <cstdint>

// ---------------------------------------------------------------------------
// MACE invariant message passing:
//   h   = node_feats @ W_up
//   m   = h[sender] * edge_attrs * edge_feats[l_of_lm]   (per edge)
//   msg = segment_sum over receiver  (stored as fp16)
//   out = msg @ ( W_lin[l] @ W_skip[elem,l] / 16 )       (grouped by element)
// Output GEMM: single-pass fp16 mma.sync (11 mantissa bits -> ~3.5e-4 error).
// ---------------------------------------------------------------------------

typedef unsigned long long u64;

#define N_MAX 6144
#define E_MAX 131072
#define NE_MAX 16
#define NG_MAX (NE_MAX * 4)
#define AST 68    // As row stride (floats) in the scalar GEMM (BM=64 + pad)

// Static device scratch (allocation-free per harness rules)
__device__ float  d_h[(size_t)N_MAX * 128];
__device__ __half d_msg_h[(size_t)N_MAX * 16 * 128];
__device__ __half d_WcT_h[(size_t)NG_MAX * 128 * 128];
__device__ int    d_sorted[E_MAX];
__device__ int    d_counts[N_MAX];         // zero-init; scan re-zeroes after use
__device__ int    d_offsets[N_MAX + 1];
__device__ int    d_cursor[N_MAX];
__device__ int    d_node_by_elem[N_MAX];
__device__ int    d_elem_off[NE_MAX + 1];
__device__ int    d_elem_cur[NE_MAX];
__device__ int    d_tile_off[NG_MAX + 1];
__device__ int    d_tile_ctr;

// --------------------------- helpers ---------------------------------------
__device__ __forceinline__ uint32_t smem_u32(const void* p) {
    uint32_t a;
    asm("{ .reg .u64 t; cvta.to.shared.u64 t, %1; cvt.u32.u64 %0, t; }"
        : "=r"(a) : "l"(p));
    return a;
}

#define CP16(dst, src) \
    asm volatile("cp.async.cg.shared.global [%0], [%1], 16;" \
        :: "r"(dst), "l"(src) : "memory")
#define CP_COMMIT() asm volatile("cp.async.commit_group;" ::: "memory")
template <int W>
__device__ __forceinline__ void cp_wait() {
    asm volatile("cp.async.wait_group %0;" :: "n"(W) : "memory");
}

#define LDSM4(r0, r1, r2, r3, addr) \
    asm volatile("ldmatrix.sync.aligned.m8n8.x4.shared.b16 {%0,%1,%2,%3}, [%4];" \
        : "=r"(r0), "=r"(r1), "=r"(r2), "=r"(r3) : "r"(addr))

#define MMA16816F16(c, a, b) \
    asm volatile("mma.sync.aligned.m16n8k16.row.col.f32.f16.f16.f32 " \
        "{%0,%1,%2,%3}, {%4,%5,%6,%7}, {%8,%9}, {%0,%1,%2,%3};" \
        : "+f"((c)[0]), "+f"((c)[1]), "+f"((c)[2]), "+f"((c)[3]) \
        : "r"((a)[0]), "r"((a)[1]), "r"((a)[2]), "r"((a)[3]), \
          "r"((b)[0]), "r"((b)[1]))

// ---------------------------------------------------------------------------
// Fused GEMM kernel (scalar fp32, BM=64, BN=128, BK=16, acc 4x8 -> no spills):
//   z == 0          : h = node_feats @ W_up          (tiles over blockIdx.x)
//   z >= 1, x <= 1  : WcT[g] rows x*64..+63 = transpose(W_lin[l] @ W_skip[g]/16)
//   z >= 1, x >= 2  : helper blocks run the receiver histogram
// ---------------------------------------------------------------------------
__global__ __launch_bounds__(256) void gemm_fused_kernel(
    const float* __restrict__ node_feats,
    const float* __restrict__ W_up,
    const float* __restrict__ W_lin,
    const float* __restrict__ W_skip,
    const int*   __restrict__ recv,
    int N, int E, int NE)
{
    const float* A;
    const float* B;
    int M;
    float scale;
    int z = blockIdx.z;
    int g = z - 1;
    int row0;

    if (z == 0) {
        A = node_feats; B = W_up; M = N; scale = 1.0f;
        row0 = blockIdx.x * 64;
    } else {
        if (blockIdx.x >= 2) {
            int nb  = gridDim.x - 2;
            int id  = (z - 1) * nb + (blockIdx.x - 2);
            int tot = (int)(gridDim.z - 1) * nb;
            for (int i = id * 256 + threadIdx.x; i < E; i += tot * 256)
                atomicAdd(&d_counts[recv[i]], 1);
            return;
        }
        int l = g & 3;
        A = W_lin  + (size_t)l * 16384;
        B = W_skip + (size_t)g * 16384;
        M = 128; scale = 1.0f / 16.0f;
        row0 = blockIdx.x * 64;
    }

    __shared__ float As[16 * AST];
    __shared__ float Bs[16 * 128];

    int tid = threadIdx.x;
    int ty = tid >> 4;      // 0..15 -> 4-row group
    int tx = tid & 15;      // 0..15 -> 4-col group (x2 halves)

    float acc[4][8];
    #pragma unroll
    for (int i = 0; i < 4; i++)
        #pragma unroll
        for (int j = 0; j < 8; j++) acc[i][j] = 0.0f;

    for (int kc = 0; kc < 128; kc += 16) {
        #pragma unroll
        for (int i = 0; i < 4; i++) {
            int idx = tid + i * 256;
            int r = idx >> 4, kk = idx & 15;
            int row = row0 + r;
            As[kk * AST + r] = (row < M) ? A[(size_t)row * 128 + kc + kk] : 0.0f;
        }
        #pragma unroll
        for (int i = 0; i < 8; i++) {
            int idx = tid + i * 256;
            int kk = idx >> 7, d = idx & 127;
            Bs[kk * 128 + d] = B[(size_t)(kc + kk) * 128 + d];
        }
        __syncthreads();
        #pragma unroll
        for (int kk = 0; kk < 16; kk++) {
            float4 a0 = *(const float4*)&As[kk * AST + ty * 4];
            float4 b0 = *(const float4*)&Bs[kk * 128 + tx * 4];
            float4 b1 = *(const float4*)&Bs[kk * 128 + 64 + tx * 4];
            float av[4] = {a0.x, a0.y, a0.z, a0.w};
            float bv[8] = {b0.x, b0.y, b0.z, b0.w, b1.x, b1.y, b1.z, b1.w};
            #pragma unroll
            for (int i = 0; i < 4; i++)
                #pragma unroll
                for (int j = 0; j < 8; j++) acc[i][j] += av[i] * bv[j];
        }
        __syncthreads();
    }

    if (z == 0) {
        #pragma unroll
        for (int i = 0; i < 4; i++) {
            int row = row0 + ty * 4 + i;
            if (row < M) {
                *(float4*)&d_h[(size_t)row * 128 + tx * 4] =
                    make_float4(acc[i][0], acc[i][1], acc[i][2], acc[i][3]);
                *(float4*)&d_h[(size_t)row * 128 + 64 + tx * 4] =
                    make_float4(acc[i][4], acc[i][5], acc[i][6], acc[i][7]);
            }
        }
    } else {
        // transposed fp16 write: WcT[g][d][c], c = Wc row, d = Wc col
        #pragma unroll
        for (int i = 0; i < 4; i++) {
            int c = row0 + ty * 4 + i;
            #pragma unroll
            for (int j = 0; j < 8; j++) {
                int d = (j < 4) ? (tx * 4 + j) : (64 + tx * 4 + (j - 4));
                d_WcT_h[((size_t)g * 128 + d) * 128 + c] =
                    __float2half_rn(acc[i][j] * scale);
            }
        }
    }
}

// Fallback hist (only if the fused grid had no helper blocks)
__global__ void hist_kernel(const int* __restrict__ recv, int E) {
    int i = blockIdx.x * blockDim.x + threadIdx.x;
    if (i < E) atomicAdd(&d_counts[recv[i]], 1);
}

// ---------------------------------------------------------------------------
// block 0: warp-shuffle scan of d_counts -> d_offsets / d_cursor, then
//          RE-ZEROES d_counts (keeps the zero invariant across graph replays)
// block 1: group nodes by element; tile prefix (64-row tiles); reset counter
// ---------------------------------------------------------------------------
__global__ void scan_elem_kernel(const int* __restrict__ node_elem, int N, int NE) {
    int tid = threadIdx.x;

    if (blockIdx.x == 1) {
        __shared__ int scnt[NE_MAX];
        if (tid < NE) scnt[tid] = 0;
        __syncthreads();
        for (int i = tid; i < N; i += blockDim.x) atomicAdd(&scnt[node_elem[i]], 1);
        __syncthreads();
        if (tid == 0) {
            int run = 0;
            for (int e = 0; e < NE; e++) { d_elem_off[e] = run; d_elem_cur[e] = run; run += scnt[e]; }
            d_elem_off[NE] = run;
            int tp = 0;
            for (int g = 0; g < NE * 4; g++) {
                int l = g & 3;
                int rows = scnt[g >> 2] * (2 * l + 1);
                d_tile_off[g] = tp;
                tp += (rows + 63) >> 6;     // 64-row tiles
            }
            d_tile_off[NE * 4] = tp;
            d_tile_ctr = 0;
        }
        __syncthreads();
        for (int i = tid; i < N; i += blockDim.x) {
            int pos = atomicAdd(&d_elem_cur[node_elem[i]], 1);
            d_node_by_elem[pos] = i;
        }
        return;
    }

    // block 0: scan (1024 threads x 6 elems = 6144 >= N_MAX)
    __shared__ int wtot[32];
    const int PER = 6;
    int lane = tid & 31, w = tid >> 5;
    int base = tid * PER;
    int cnt[PER];
    int run = 0;
    #pragma unroll
    for (int i = 0; i < PER; i++) {
        cnt[i] = (base + i < N) ? d_counts[base + i] : 0;
        run += cnt[i];
    }
    int ws = run;
    #pragma unroll
    for (int o = 1; o < 32; o <<= 1) {
        int t = __shfl_up_sync(0xffffffffu, ws, o);
        if (lane >= o) ws += t;
    }
    if (lane == 31) wtot[w] = ws;
    __syncthreads();
    if (w == 0) {
        int v = wtot[lane];
        #pragma unroll
        for (int o = 1; o < 32; o <<= 1) {
            int t = __shfl_up_sync(0xffffffffu, v, o);
            if (lane >= o) v += t;
        }
        wtot[lane] = v;
    }
    __syncthreads();
    int acc = (w ? wtot[w - 1] : 0) + (ws - run);
    if (tid == 0) d_offsets[0] = 0;
    #pragma unroll
    for (int i = 0; i < PER; i++) {
        int idx = base + i;
        if (idx < N) {
            d_cursor[idx] = acc;
            acc += cnt[i];
            d_offsets[idx + 1] = acc;
            d_counts[idx] = 0;     // restore zero invariant for next replay
        }
    }
}

__global__ void scatter_kernel(const int* __restrict__ recv, int E) {
    int i = blockIdx.x * blockDim.x + threadIdx.x;
    if (i < E) {
        int pos = atomicAdd(&d_cursor[recv[i]], 1);
        d_sorted[pos] = i;
    }
}

// ---------------------------------------------------------------------------
// Edge accumulation (R8 structure, measured best): one CTA per node, 256
// threads. Thread = (channel c = tid&127, parity par = tid>>7), 16 lm accs
// per thread, depth-2 register pipeline, combined via smem. Epilogue writes
// msg as fp16. l_of_lm: [0, 1,1,1, 2,2,2,2,2, 3,3,3,3,3,3,3]
// ---------------------------------------------------------------------------
__global__ __launch_bounds__(256) void edge_accum_kernel(
    const float* __restrict__ edge_attrs,   // [E,16]
    const float* __restrict__ edge_feats,   // [E,4,128]
    const int*   __restrict__ sender)       // [E]
{
    int n = blockIdx.x;
    int tid = threadIdx.x;
    int c = tid & 127;
    int par = tid >> 7;

    __shared__ float s_attr[32][16];
    __shared__ int   s_e[32];
    __shared__ int   s_send[32];
    __shared__ float s_part[16][128];

    float acc[16];
    #pragma unroll
    for (int i = 0; i < 16; i++) acc[i] = 0.0f;

    int beg = d_offsets[n];
    int end = d_offsets[n + 1];

    for (int base = beg; base < end; base += 32) {
        int m = end - base;
        if (m > 32) m = 32;
        if (tid < m) {
            int ee = d_sorted[base + tid];
            s_e[tid] = ee;
            s_send[tid] = sender[ee];
        }
        for (int i = tid; i < m * 16; i += 256) {
            int j = i >> 4;
            s_attr[j][i & 15] = __ldcs(&edge_attrs[(size_t)d_sorted[base + j] * 16 + (i & 15)]);
        }
        __syncthreads();

        int j = par;
        float A0[5] = {0.f, 0.f, 0.f, 0.f, 0.f};
        float A1[5] = {0.f, 0.f, 0.f, 0.f, 0.f};
        if (j < m) {
            const float* efp = edge_feats + (size_t)s_e[j] * 512;
            A0[0] = __ldcs(efp + c);       A0[1] = __ldcs(efp + 128 + c);
            A0[2] = __ldcs(efp + 256 + c); A0[3] = __ldcs(efp + 384 + c);
            A0[4] = __ldg(&d_h[(size_t)s_send[j] * 128 + c]);
        }
        if (j + 2 < m) {
            const float* efp = edge_feats + (size_t)s_e[j + 2] * 512;
            A1[0] = __ldcs(efp + c);       A1[1] = __ldcs(efp + 128 + c);
            A1[2] = __ldcs(efp + 256 + c); A1[3] = __ldcs(efp + 384 + c);
            A1[4] = __ldg(&d_h[(size_t)s_send[j + 2] * 128 + c]);
        }
        while (j < m) {
            float A2[5] = {0.f, 0.f, 0.f, 0.f, 0.f};
            if (j + 4 < m) {
                const float* efp = edge_feats + (size_t)s_e[j + 4] * 512;
                A2[0] = __ldcs(efp + c);       A2[1] = __ldcs(efp + 128 + c);
                A2[2] = __ldcs(efp + 256 + c); A2[3] = __ldcs(efp + 384 + c);
                A2[4] = __ldg(&d_h[(size_t)s_send[j + 4] * 128 + c]);
            }
            const float* at = s_attr[j];
            float hs = A0[4];
            float p0 = hs * A0[0], p1 = hs * A0[1], p2 = hs * A0[2], p3 = hs * A0[3];
            acc[0]  += p0 * at[0];
            acc[1]  += p1 * at[1];
            acc[2]  += p1 * at[2];
            acc[3]  += p1 * at[3];
            acc[4]  += p2 * at[4];
            acc[5]  += p2 * at[5];
            acc[6]  += p2 * at[6];
            acc[7]  += p2 * at[7];
            acc[8]  += p2 * at[8];
            acc[9]  += p3 * at[9];
            acc[10] += p3 * at[10];
            acc[11] += p3 * at[11];
            acc[12] += p3 * at[12];
            acc[13] += p3 * at[13];
            acc[14] += p3 * at[14];
            acc[15] += p3 * at[15];
            #pragma unroll
            for (int q = 0; q < 5; q++) { A0[q] = A1[q]; A1[q] = A2[q]; }
            j += 2;
        }
        __syncthreads();
    }

    if (par) {
        #pragma unroll
        for (int lm = 0; lm < 16; lm++) s_part[lm][c] = acc[lm];
    }
    __syncthreads();
    if (!par) {
        size_t ob = (size_t)n * 2048 + c;
        #pragma unroll
        for (int lm = 0; lm < 16; lm++)
            d_msg_h[ob + (size_t)lm * 128] =
                __float2half_rn(acc[lm] + s_part[lm][c]);
    }
}

// ---------------------------------------------------------------------------
// Output GEMM via single-pass fp16 mma.sync (fp32 accumulate). Persistent
// tile queue, BM=64 tiles, smem A+B = 52KB -> 3 CTAs/SM for overlap.
// Tile = 64 gathered msg rows x 128 cols x K=128; 8 warps, warp tile 32x32.
// 64 MMAs/warp/tile (1/3 of the hi/lo version). Fills are pure cp.async.
// ---------------------------------------------------------------------------
#define ROWP 136
#define A_BUF (64 * ROWP * 2)               // 17408
#define B_BUF (128 * ROWP * 2)              // 34816
#define DSMEM_BYTES (A_BUF + B_BUF)         // 52224

__global__ __launch_bounds__(256, 3) void out_gemm_mma(float* __restrict__ out, int NE)
{
    extern __shared__ __half smb[];
    __half* A_s = smb;

    __shared__ int s_off[64];
    __shared__ int s_toff[NG_MAX + 1];
    __shared__ int s_eoff[NE_MAX + 1];
    __shared__ int s_tile;

    int tid = threadIdx.x, wid = tid >> 5, lid = tid & 31;
    int NG = NE * 4;
    if (tid <= NG) s_toff[tid] = d_tile_off[tid];
    if (tid <= NE) s_eoff[tid] = d_elem_off[tid];
    __syncthreads();
    int ntiles = s_toff[NG];

    int wm0 = (wid & 1) * 32;     // warp row base (0/32)
    int wn0 = (wid >> 1) * 32;    // warp col base (0..96)

    // ldmatrix lane geometry (byte offsets within a buffer)
    int a_row0 = wm0 + ((lid >> 3) & 1) * 8 + (lid & 7);
    int a_kadd = ((lid >> 4) & 1) * 8;
    uint32_t aoff[2];
    #pragma unroll
    for (int mt = 0; mt < 2; mt++)
        aoff[mt] = (uint32_t)(((a_row0 + mt * 16) * ROWP + a_kadd) * 2);
    int b_row0 = wn0 + ((lid >> 4) & 1) * 8 + (lid & 7);
    int b_kadd = ((lid >> 3) & 1) * 8;
    uint32_t boff[2];
    #pragma unroll
    for (int p = 0; p < 2; p++)
        boff[p] = (uint32_t)(((b_row0 + p * 16) * ROWP + b_kadd) * 2);

    uint32_t sA = smem_u32(smb);
    uint32_t sB = sA + A_BUF;

    int g_prev = -1;

    while (true) {
        if (tid == 0) s_tile = atomicAdd(&d_tile_ctr, 1);
        __syncthreads();
        int t = s_tile;
        if (t >= ntiles) break;

        int g = 0;
        while (s_toff[g + 1] <= t) g++;
        int l = g & 3, e = g >> 2;
        int tw = 2 * l + 1;
        int cbeg = s_eoff[e];
        int rows = (s_eoff[e + 1] - cbeg) * tw;
        int tile = (t - s_toff[g]) * 64;
        bool fillB = (g != g_prev);
        g_prev = g;

        if (tid < 64) {
            int rr = tile + tid;
            int off = -1;
            if (rr < rows) {
                int node = d_node_by_elem[cbeg + rr / tw];
                off = (node * 16 + l * l + rr % tw) * 128;
            }
            s_off[tid] = off;
        }
        __syncthreads();

        // --- fill A via cp.async (64 rows x 16 x 16B jobs, 4 per thread) ---
        #pragma unroll
        for (int q = 0; q < 4; q++) {
            int i = tid + q * 256;
            int r = i >> 4, w = i & 15;
            int off = s_off[r];
            uint32_t d = (uint32_t)((r * ROWP + w * 8) * 2);
            if (off >= 0) {
                CP16(sA + d, d_msg_h + (size_t)off + w * 8);
            } else {
                *(uint4*)(A_s + r * ROWP + w * 8) = make_uint4(0, 0, 0, 0);
            }
        }
        // --- fill B via cp.async only when the group changed ---
        if (fillB) {
            #pragma unroll
            for (int q = 0; q < 8; q++) {
                int i = tid + q * 256;
                int r = i >> 4, w = i & 15;
                uint32_t d = (uint32_t)((r * ROWP + w * 8) * 2);
                CP16(sB + d, d_WcT_h + ((size_t)g * 128 + r) * 128 + w * 8);
            }
        }
        CP_COMMIT();
        cp_wait<0>();
        __syncthreads();

        // --- compute (single fp16 pass) ---
        float acc[2][4][4];
        #pragma unroll
        for (int mt = 0; mt < 2; mt++)
            #pragma unroll
            for (int nt = 0; nt < 4; nt++)
                #pragma unroll
                for (int q = 0; q < 4; q++) acc[mt][nt][q] = 0.0f;

        #pragma unroll
        for (int ks = 0; ks < 8; ks++) {
            uint32_t kb = (uint32_t)(ks * 16 * 2);
            uint32_t ah[2][4];
            #pragma unroll
            for (int mt = 0; mt < 2; mt++)
                LDSM4(ah[mt][0], ah[mt][1], ah[mt][2], ah[mt][3], sA + aoff[mt] + kb);
            uint32_t bh[4][2];
            #pragma unroll
            for (int p = 0; p < 2; p++) {
                uint32_t r0, r1, r2, r3;
                LDSM4(r0, r1, r2, r3, sB + boff[p] + kb);
                bh[2 * p][0] = r0; bh[2 * p][1] = r1;
                bh[2 * p + 1][0] = r2; bh[2 * p + 1][1] = r3;
            }
            #pragma unroll
            for (int mt = 0; mt < 2; mt++)
                #pragma unroll
                for (int nt = 0; nt < 4; nt++)
                    MMA16816F16(acc[mt][nt], ah[mt], bh[nt]);
        }

        // --- epilogue: scatter to out via s_off ---
        #pragma unroll
        for (int mt = 0; mt < 2; mt++) {
            int r0 = wm0 + mt * 16 + (lid >> 2);
            int off0 = s_off[r0];
            int off1 = s_off[r0 + 8];
            #pragma unroll
            for (int nt = 0; nt < 4; nt++) {
                int col = wn0 + nt * 8 + (lid & 3) * 2;
                if (off0 >= 0)
                    *(float2*)&out[(size_t)off0 + col] =
                        make_float2(acc[mt][nt][0], acc[mt][nt][1]);
                if (off1 >= 0)
                    *(float2*)&out[(size_t)off1 + col] =
                        make_float2(acc[mt][nt][2], acc[mt][nt][3]);
            }
        }
        __syncthreads();   // protect smem/s_off before next tile
    }
}

// ---------------------------------------------------------------------------
// Launch
// ---------------------------------------------------------------------------
extern "C" void kernel_launch(void* const* d_in, const int* in_sizes, int n_in,
                              void* d_out, int out_size)
{
    const float* node_feats = (const float*)d_in[0];   // [N,128]
    const float* edge_attrs = (const float*)d_in[1];   // [E,16]
    const float* edge_feats = (const float*)d_in[2];   // [E,512]
    const float* W_up       = (const float*)d_in[3];   // [128,128]
    const float* W_lin      = (const float*)d_in[4];   // [4,128,128]
    const float* W_skip     = (const float*)d_in[5];   // [NE,4,128,128]
    const int*   edge_index = (const int*)d_in[6];     // [2,E]
    const int*   node_elem  = (const int*)d_in[7];     // [N]

    int N  = in_sizes[7];
    int E  = in_sizes[1] / 16;
    int NE = in_sizes[5] / (4 * 128 * 128);

    const int* sender = edge_index;
    const int* recv   = edge_index + E;

    int gx = (N + 63) / 64;

    // immediate host-side attribute set (not stream-ordered; capture-safe)
    cudaFuncSetAttribute(out_gemm_mma,
                         cudaFuncAttributeMaxDynamicSharedMemorySize, DSMEM_BYTES);

    // 0. h GEMM + WcT fp16 + receiver histogram (counts pre-zeroed:
    //    initial load zeros + scan re-zeroes each replay)
    gemm_fused_kernel<<<dim3(gx, 1, 1 + NE * 4), 256>>>(
        node_feats, W_up, W_lin, W_skip, recv, N, E, NE);
    if (gx < 3)   // degenerate: no helper blocks existed
        hist_kernel<<<(E + 255) / 256, 256>>>(recv, E);

    // 1. scan (+ re-zero counts) + element grouping + tile prefix (64-row)
    scan_elem_kernel<<<2, 1024>>>(node_elem, N, NE);

    // 2. counting-sort scatter
    scatter_kernel<<<(E + 255) / 256, 256>>>(recv, E);

    // 3. per-node edge accumulation -> msg (fp16)
    edge_accum_kernel<<<N, 256>>>(edge_attrs, edge_feats, sender);

    // 4. output GEMM on tensor cores (single-pass fp16, 3 CTAs/SM)
    out_gemm_mma<<<444, 256, DSMEM_BYTES>>>((float*)d_out, NE);
}